// round 10
// baseline (speedup 1.0000x reference)
#include <cuda_runtime.h>
#include <stdint.h>

// ---------------------------------------------------------------------------
// DownsampleWithPruning — gather formulation, output written exactly once.
// Keyspace: b<<24 | x<<16 | y<<8 | z  in [0, 2^26)
//
//   k_setup : g_state reset; refbit OR; g_table[key]=i+1 + parent bitmap OR
//   k_all   : per chunk: dual warp-shuffle scan + decoupled lookback ->
//             coords+mask emit, coalesced zero-fill of the chunk's feats slice,
//             warp-per-masked-row gather conv (+bias), plain stores.
//             Pad blocks (idx>=NCHUNK) write rows [M,N).
// ---------------------------------------------------------------------------

#define WORDS   (1 << 20)       // 2^26 keys / 64
#define NCHUNK  1024            // scan chunks (1024 words each)
#define CWORDS  1024
#define PADB    160             // pad blocks
#define CAP     1024            // smem masked-list capacity per chunk
#define MASK21  0x1FFFFFull
#define FULLM   0xffffffffu

__device__ unsigned long long g_bitmap[WORDS];   // parent-key occupancy (8MB)
__device__ unsigned long long g_refbit[WORDS];   // ref-key occupancy (8MB)
__device__ unsigned long long g_state[NCHUNK];   // flag<<62 | rank<<21 | mask
__device__ int g_table[1 << 26];                 // key -> input idx + 1 (256MB)

// ---- setup: state reset + ref bitmap + table + parent bitmap ----------------
__global__ void __launch_bounds__(256) k_setup(const int* __restrict__ coords, int N,
                                               const int* __restrict__ rc, int NR) {
    int tid = blockIdx.x * blockDim.x + threadIdx.x;
    int T = gridDim.x * blockDim.x;
    for (int i = tid; i < NCHUNK; i += T) g_state[i] = 0ull;

    const int4* rc4 = (const int4*)rc;
    for (int i = tid; i < NR; i += T) {
        int4 c = rc4[i];
        int key = (c.x << 24) | (c.y << 16) | (c.z << 8) | c.w;
        atomicOr(&g_refbit[key >> 6], 1ull << (key & 63));
    }
    const int4* c4 = (const int4*)coords;
    for (int i = tid; i < N; i += T) {
        int4 c = c4[i];
        int key  = (c.x << 24) | (c.y << 16) | (c.z << 8) | c.w;
        g_table[key] = i + 1;                       // unique writer per key
        int pkey = key & ~0x00010101;
        atomicOr(&g_bitmap[pkey >> 6], 1ull << (pkey & 63));
    }
}

// ---- the single output writer ------------------------------------------------
__global__ void __launch_bounds__(256) k_all(const float* __restrict__ feats,
                                             const float* __restrict__ W,
                                             const float* __restrict__ bias,
                                             float* __restrict__ out,
                                             int N,
                                             long long featBase,
                                             long long maskBase) {
    __shared__ unsigned long long s_wsum[8];
    __shared__ int s_exR;
    __shared__ int s_mrank[CAP];
    __shared__ int s_mkey[CAP];

    const int tid  = threadIdx.x;
    const int lane = tid & 31;
    const int wid  = tid >> 5;
    const int b    = blockIdx.x;
    const float4 zero4 = make_float4(0.f, 0.f, 0.f, 0.f);

    // ---------- pad blocks: rows [M, N) ----------
    if (b >= NCHUNK) {
        unsigned long long v;
        do {
            v = *((volatile unsigned long long*)&g_state[NCHUNK - 1]);
        } while ((v >> 62) != 2ull);
        int M = (int)((v >> 21) & MASK21);
        int pb = b - NCHUNK;
        int pt = pb * 256 + tid;
        int PT = PADB * 256;
        float4 neg1 = make_float4(-1.f, -1.f, -1.f, -1.f);
        for (int r = M + pt; r < N; r += PT) {
            __stcs(&((float4*)out)[r], neg1);
            __stcs(&out[maskBase + r], 0.0f);
        }
        float4* pf = (float4*)(out + featBase);
        long long f0 = (long long)M * 16, f1 = (long long)N * 16;
        for (long long i = f0 + pt; i < f1; i += PT) __stcs(&pf[i], zero4);
        return;
    }

    // ---------- chunk blocks ----------
    int base = b * CWORDS + tid * 4;
    unsigned long long w[4], mw[4];
    int s = 0, m = 0;
#pragma unroll
    for (int j = 0; j < 4; j++) {
        w[j]  = g_bitmap[base + j];
        mw[j] = w[j] & g_refbit[base + j];
        s += __popcll(w[j]);
        m += __popcll(mw[j]);
    }
    // dual warp-shuffle scan: packed (rank<<32 | mask)
    unsigned long long x = ((unsigned long long)s << 32) | (unsigned)m;
#pragma unroll
    for (int o = 1; o < 32; o <<= 1) {
        unsigned long long y = __shfl_up_sync(FULLM, x, o);
        if (lane >= o) x += y;
    }
    if (lane == 31) s_wsum[wid] = x;
    __syncthreads();
    if (wid == 0) {
        unsigned long long t = (lane < 8) ? s_wsum[lane] : 0ull;
#pragma unroll
        for (int o = 1; o < 8; o <<= 1) {
            unsigned long long y = __shfl_up_sync(FULLM, t, o);
            if (lane >= o) t += y;
        }
        if (lane < 8) s_wsum[lane] = t;
    }
    __syncthreads();
    unsigned long long wb = wid ? s_wsum[wid - 1] : 0ull;
    unsigned long long incl = wb + x;
    int thrExR = (int)(incl >> 32) - s;
    int thrExM = (int)(incl & 0xFFFFFFFFull) - m;
    int aggR = (int)(s_wsum[7] >> 32);
    int aggM = (int)(s_wsum[7] & 0xFFFFFFFFull);

    if (tid == 0) {
        long long exR = 0;
        if (b == 0) {
            atomicExch(&g_state[0], (2ull << 62) |
                       ((unsigned long long)aggR << 21) | (unsigned long long)aggM);
        } else {
            atomicExch(&g_state[b], (1ull << 62) |
                       ((unsigned long long)aggR << 21) | (unsigned long long)aggM);
            int j = b - 1;
            while (true) {
                unsigned long long v = *((volatile unsigned long long*)&g_state[j]);
                unsigned f = (unsigned)(v >> 62);
                if (f == 0) continue;
                exR += (long long)((v >> 21) & MASK21);
                if (f == 2) break;
                j--;
            }
            atomicExch(&g_state[b], (2ull << 62) |
                       ((unsigned long long)(exR + aggR) << 21) |
                       (unsigned long long)aggM);   // mask field local only
        }
        s_exR = (int)exR;
    }
    __syncthreads();

    // emit coords + mask; collect masked (rank,key) deterministically
    int rank = s_exR + thrExR;
    int mIdx = thrExM;
#pragma unroll
    for (int j = 0; j < 4; j++) {
        unsigned long long ww = w[j], mm = mw[j];
        int keyhi = (base + j) << 6;
        while (ww) {
            int bpos = __ffsll((long long)ww) - 1;
            ww &= ww - 1;
            int k = keyhi | bpos;
            __stcs(&((float4*)out)[rank],
                   make_float4((float)(k >> 24), (float)((k >> 16) & 255),
                               (float)((k >> 8) & 255), (float)(k & 255)));
            bool msk = (mm >> bpos) & 1ull;
            __stcs(&out[maskBase + rank], msk ? 1.0f : 0.0f);
            if (msk) {
                if (mIdx < CAP) { s_mrank[mIdx] = rank; s_mkey[mIdx] = k; }
                mIdx++;
            }
            rank++;
        }
    }
    __syncthreads();

    // coalesced zero-fill of this chunk's contiguous feats slice
    {
        float4* pf = (float4*)(out + featBase + (long long)s_exR * 64);
        int n4 = aggR * 16;
        for (int i = tid; i < n4; i += 256) __stcs(&pf[i], zero4);
    }
    __syncthreads();

    // masked rows: warp-per-row gather conv + bias (overwrites zeros)
    int mc = aggM < CAP ? aggM : CAP;
    float b0 = __ldg(&bias[lane]);
    float b1 = __ldg(&bias[32 + lane]);
    for (int i = wid; i < mc; i += 8) {
        int r = s_mrank[i];
        int k = s_mkey[i];
        float a0 = b0, a1 = b1;
#pragma unroll
        for (int tap = 0; tap < 8; tap++) {
            int ck = k | ((tap & 4) << 14) | ((tap & 2) << 7) | (tap & 1);
            int idx = g_table[ck];
            if (idx) {
                float f = __ldg(&feats[(long long)(idx - 1) * 32 + lane]);
                const float* Wt = W + tap * 2048;
#pragma unroll
                for (int j = 0; j < 32; j++) {
                    float fj = __shfl_sync(FULLM, f, j);
                    a0 += fj * __ldg(&Wt[j * 64 + lane]);
                    a1 += fj * __ldg(&Wt[j * 64 + 32 + lane]);
                }
            }
        }
        float* dst = out + featBase + (long long)r * 64;
        dst[lane] = a0;
        dst[32 + lane] = a1;
    }

    // overflow fallback (aggM > CAP): owner thread computes rows serially.
    if (aggM > CAP) {
        int rank2 = s_exR + thrExR;
        int mIdx2 = thrExM;
#pragma unroll
        for (int j = 0; j < 4; j++) {
            unsigned long long ww = w[j], mm = mw[j];
            int keyhi = (base + j) << 6;
            while (ww) {
                int bpos = __ffsll((long long)ww) - 1;
                ww &= ww - 1;
                if ((mm >> bpos) & 1ull) {
                    if (mIdx2 >= CAP) {
                        int k = keyhi | bpos;
                        float* dst = out + featBase + (long long)rank2 * 64;
                        for (int h = 0; h < 64; h++) {
                            float acc = __ldg(&bias[h]);
                            for (int tap = 0; tap < 8; tap++) {
                                int ck = k | ((tap & 4) << 14) | ((tap & 2) << 7) | (tap & 1);
                                int idx = g_table[ck];
                                if (idx)
                                    for (int q = 0; q < 32; q++)
                                        acc += __ldg(&feats[(long long)(idx - 1) * 32 + q]) *
                                               __ldg(&W[tap * 2048 + q * 64 + h]);
                            }
                            dst[h] = acc;
                        }
                    }
                    mIdx2++;
                }
                rank2++;
            }
        }
    }
}

extern "C" void kernel_launch(void* const* d_in, const int* in_sizes, int n_in,
                              void* d_out, int out_size) {
    const float* feats  = (const float*)d_in[0];
    const float* W      = (const float*)d_in[1];
    const float* bias   = (const float*)d_in[2];
    const int*   coords = (const int*)d_in[3];
    const int*   ref    = (const int*)d_in[4];
    float* out = (float*)d_out;

    int N  = in_sizes[3] / 4;
    int NR = in_sizes[4] / 4;
    long long featBase = 4LL * N;
    long long maskBase = (long long)out_size - N;   // == 68N

    k_setup<<<1184, 256>>>(coords, N, ref, NR);
    k_all<<<NCHUNK + PADB, 256>>>(feats, W, bias, out, N, featBase, maskBase);
}

// round 11
// speedup vs baseline: 1.2518x; 1.2518x over previous
#include <cuda_runtime.h>
#include <stdint.h>

// ---------------------------------------------------------------------------
// DownsampleWithPruning — sparse stride-2 conv (2x2x2) + prune by ref set.
// Keyspace: b<<24 | x<<16 | y<<8 | z  in [0, 2^26)
//
// DAG:
//   s0: k_fill     260MB feats+mask zeros (dedicated streaming writer)
//   sB: k_setup    state reset + refbit OR + g_table[key]=i+1 + parent bitmap
//       k_scanemit warp-shuffle dual scan + lookback -> coords + masked list
//   s0: join -> k_gather  warp-per-masked-row: bias + 8-tap gather conv,
//               plain full-row stores + mask=1; pads coords [M,N)
// ---------------------------------------------------------------------------

#define WORDS   (1 << 20)       // 2^26 keys / 64
#define NCHUNK  1024            // scan chunks (1024 words each)
#define CWORDS  1024
#define MASK21  0x1FFFFFull
#define FULLM   0xffffffffu

__device__ unsigned long long g_bitmap[WORDS];   // parent-key occupancy (8MB)
__device__ unsigned long long g_refbit[WORDS];   // ref-key occupancy (8MB)
__device__ unsigned long long g_state[NCHUNK];   // flag<<62 | rank<<21 | mask
__device__ int g_table[1 << 26];                 // key -> input idx + 1 (256MB)
__device__ int2 g_mlist[1 << 20];                // masked (rank, key)
__device__ int g_M;                              // unique outputs
__device__ int g_mTotal;                         // masked outputs

// ---- dedicated streaming zero fill ------------------------------------------
__global__ void __launch_bounds__(256) k_fill(float* __restrict__ out,
                                              long long startFloat,
                                              long long numFloats) {
    long long n4 = numFloats >> 2;
    float4* p = (float4*)(out + startFloat);
    float4 z = make_float4(0.f, 0.f, 0.f, 0.f);
    long long T = (long long)gridDim.x * blockDim.x;
    long long i = (long long)blockIdx.x * blockDim.x + threadIdx.x;
    for (; i + T < n4; i += 2 * T) {
        __stcs(&p[i], z);
        __stcs(&p[i + T], z);
    }
    if (i < n4) __stcs(&p[i], z);
    long long tail = numFloats & 3;
    if (blockIdx.x == 0 && threadIdx.x < tail)
        out[startFloat + (n4 << 2) + threadIdx.x] = 0.f;
}

// ---- setup: state reset + ref bitmap + key table + parent bitmap ------------
__global__ void __launch_bounds__(256) k_setup(const int* __restrict__ coords, int N,
                                               const int* __restrict__ rc, int NR) {
    int tid = blockIdx.x * blockDim.x + threadIdx.x;
    int T = gridDim.x * blockDim.x;
    for (int i = tid; i < NCHUNK; i += T) g_state[i] = 0ull;

    const int4* rc4 = (const int4*)rc;
    for (int i = tid; i < NR; i += T) {
        int4 c = rc4[i];
        int key = (c.x << 24) | (c.y << 16) | (c.z << 8) | c.w;
        atomicOr(&g_refbit[key >> 6], 1ull << (key & 63));
    }
    const int4* c4 = (const int4*)coords;
    for (int i = tid; i < N; i += T) {
        int4 c = c4[i];
        int key  = (c.x << 24) | (c.y << 16) | (c.z << 8) | c.w;
        g_table[key] = i + 1;                       // unique writer per key
        int pkey = key & ~0x00010101;
        atomicOr(&g_bitmap[pkey >> 6], 1ull << (pkey & 63));
    }
}

// ---- dual warp-shuffle scan + lookback; emit coords + masked (rank,key) -----
__global__ void __launch_bounds__(256) k_scanemit(float* __restrict__ out) {
    __shared__ unsigned long long s_wsum[8];
    __shared__ int s_exR, s_exM;
    const int tid  = threadIdx.x;
    const int lane = tid & 31;
    const int wid  = tid >> 5;
    const int b    = blockIdx.x;

    int base = b * CWORDS + tid * 4;
    unsigned long long w[4], mw[4];
    int s = 0, m = 0;
#pragma unroll
    for (int j = 0; j < 4; j++) {
        w[j]  = g_bitmap[base + j];
        mw[j] = w[j] & g_refbit[base + j];
        s += __popcll(w[j]);
        m += __popcll(mw[j]);
    }
    unsigned long long x = ((unsigned long long)s << 32) | (unsigned)m;
#pragma unroll
    for (int o = 1; o < 32; o <<= 1) {
        unsigned long long y = __shfl_up_sync(FULLM, x, o);
        if (lane >= o) x += y;
    }
    if (lane == 31) s_wsum[wid] = x;
    __syncthreads();
    if (wid == 0) {
        unsigned long long t = (lane < 8) ? s_wsum[lane] : 0ull;
#pragma unroll
        for (int o = 1; o < 8; o <<= 1) {
            unsigned long long y = __shfl_up_sync(FULLM, t, o);
            if (lane >= o) t += y;
        }
        if (lane < 8) s_wsum[lane] = t;
    }
    __syncthreads();
    unsigned long long incl = (wid ? s_wsum[wid - 1] : 0ull) + x;
    int thrExR = (int)(incl >> 32) - s;
    int thrExM = (int)(incl & 0xFFFFFFFFull) - m;
    int aggR = (int)(s_wsum[7] >> 32);
    int aggM = (int)(s_wsum[7] & 0xFFFFFFFFull);

    if (tid == 0) {
        long long exR = 0, exM = 0;
        if (b == 0) {
            atomicExch(&g_state[0], (2ull << 62) |
                       ((unsigned long long)aggR << 21) | (unsigned long long)aggM);
        } else {
            atomicExch(&g_state[b], (1ull << 62) |
                       ((unsigned long long)aggR << 21) | (unsigned long long)aggM);
            int j = b - 1;
            while (true) {
                unsigned long long v = *((volatile unsigned long long*)&g_state[j]);
                unsigned f = (unsigned)(v >> 62);
                if (f == 0) continue;
                exR += (long long)((v >> 21) & MASK21);
                exM += (long long)(v & MASK21);
                if (f == 2) break;
                j--;
            }
            atomicExch(&g_state[b], (2ull << 62) |
                       ((unsigned long long)(exR + aggR) << 21) |
                       (unsigned long long)(exM + aggM));
        }
        s_exR = (int)exR;
        s_exM = (int)exM;
        if (b == NCHUNK - 1) { g_M = (int)exR + aggR; g_mTotal = (int)exM + aggM; }
    }
    __syncthreads();

    int rank  = s_exR + thrExR;
    int mrank = s_exM + thrExM;
#pragma unroll
    for (int j = 0; j < 4; j++) {
        unsigned long long ww = w[j], mm = mw[j];
        int keyhi = (base + j) << 6;
        while (ww) {
            int bpos = __ffsll((long long)ww) - 1;
            ww &= ww - 1;
            int k = keyhi | bpos;
            __stcs(&((float4*)out)[rank],
                   make_float4((float)(k >> 24), (float)((k >> 16) & 255),
                               (float)((k >> 8) & 255), (float)(k & 255)));
            if ((mm >> bpos) & 1ull) g_mlist[mrank++] = make_int2(rank, k);
            rank++;
        }
    }
}

// ---- tail: warp-per-masked-row gather conv + mask=1 + coords pad ------------
__global__ void __launch_bounds__(256) k_gather(const float* __restrict__ feats,
                                                const float* __restrict__ W,
                                                const float* __restrict__ bias,
                                                float* __restrict__ out,
                                                int N,
                                                long long featBase,
                                                long long maskBase) {
    const int lane = threadIdx.x & 31;
    const int gtid = blockIdx.x * blockDim.x + threadIdx.x;
    const int Tthr = gridDim.x * blockDim.x;
    const int gw   = gtid >> 5;
    const int totalWarps = Tthr >> 5;

    // pad coords rows [M, N)
    int M = g_M;
    float4 neg1 = make_float4(-1.f, -1.f, -1.f, -1.f);
    for (int r = M + gtid; r < N; r += Tthr)
        __stcs(&((float4*)out)[r], neg1);

    float b0 = __ldg(&bias[lane]);
    float b1 = __ldg(&bias[32 + lane]);
    int mc = g_mTotal;
    for (int i = gw; i < mc; i += totalWarps) {
        int2 e = g_mlist[i];
        int r = e.x, k = e.y;
        float a0 = b0, a1 = b1;
#pragma unroll
        for (int tap = 0; tap < 8; tap++) {
            int ck = k | ((tap & 4) << 14) | ((tap & 2) << 7) | (tap & 1);
            int idx = __ldg(&g_table[ck]);
            if (idx) {
                float f = __ldg(&feats[(long long)(idx - 1) * 32 + lane]);
                const float* Wt = W + tap * 2048;
#pragma unroll
                for (int j = 0; j < 32; j++) {
                    float fj = __shfl_sync(FULLM, f, j);
                    a0 += fj * __ldg(&Wt[j * 64 + lane]);
                    a1 += fj * __ldg(&Wt[j * 64 + 32 + lane]);
                }
            }
        }
        float* dst = out + featBase + (long long)r * 64;
        dst[lane] = a0;
        dst[32 + lane] = a1;
        if (lane == 0) out[maskBase + r] = 1.0f;
    }
}

// ---- streams/events created at load time (no device-memory allocation) -----
static cudaStream_t g_sB;
static cudaEvent_t  g_evFork, g_evEmit;
namespace {
struct ResInit {
    ResInit() {
        cudaStreamCreateWithFlags(&g_sB, cudaStreamNonBlocking);
        cudaEventCreateWithFlags(&g_evFork, cudaEventDisableTiming);
        cudaEventCreateWithFlags(&g_evEmit, cudaEventDisableTiming);
    }
};
static ResInit g_resInit;
}

extern "C" void kernel_launch(void* const* d_in, const int* in_sizes, int n_in,
                              void* d_out, int out_size) {
    const float* feats  = (const float*)d_in[0];
    const float* W      = (const float*)d_in[1];
    const float* bias   = (const float*)d_in[2];
    const int*   coords = (const int*)d_in[3];
    const int*   ref    = (const int*)d_in[4];
    float* out = (float*)d_out;

    int N  = in_sizes[3] / 4;
    int NR = in_sizes[4] / 4;
    long long featBase = 4LL * N;
    long long maskBase = (long long)out_size - N;          // == 68N
    long long zeroLen  = (long long)out_size - featBase;   // feats + mask (65N)

    cudaEventRecord(g_evFork, 0);
    cudaStreamWaitEvent(g_sB, g_evFork, 0);

    // s0: dedicated streaming fill of feats + mask
    k_fill<<<592, 256, 0, 0>>>(out, featBase, zeroLen);

    // sB: setup (bitmaps + table) -> scanemit (coords + masked list)
    k_setup<<<1184, 256, 0, g_sB>>>(coords, N, ref, NR);
    k_scanemit<<<NCHUNK, 256, 0, g_sB>>>(out);
    cudaEventRecord(g_evEmit, g_sB);

    // s0: join -> gather tail (plain stores over the zero fill)
    cudaStreamWaitEvent(0, g_evEmit, 0);
    k_gather<<<1184, 256, 0, 0>>>(feats, W, bias, out, N, featBase, maskBase);
}

// round 12
// speedup vs baseline: 1.3883x; 1.1091x over previous
#include <cuda_runtime.h>
#include <stdint.h>

// ---------------------------------------------------------------------------
// DownsampleWithPruning — sparse stride-2 conv (2x2x2) + prune by ref set.
// Keyspace: b<<24 | x<<16 | y<<8 | z  in [0, 2^26)
//
// DAG (5 launches per call):
//   s0: k_fill     260MB feats+mask zeros (dedicated streaming writer)
//   sB: k_ref      state/ovfl reset + ref bitmap
//       k_main     parent bitmap + per-(tap,block) contribution lists
//       k_scanemit warp-shuffle dual scan + lookback -> coords, rankBase,
//                  masked-rank list (atomic-free)
//   s0: join -> k_biasconv  pad + mask/bias + tap-pinned conv (W regs once)
// ---------------------------------------------------------------------------

#define WORDS   (1 << 20)       // 2^26 keys / 64
#define NCHUNK  1024            // scan chunks (1024 words each)
#define CWORDS  1024
#define MASK21  0x1FFFFFull
#define FULLM   0xffffffffu
#define FCH     1024            // items per k_main block
#define FBLKMAX 1024
#define LCAP    64

__device__ unsigned long long g_bitmap[WORDS];   // parent-key occupancy (8MB)
__device__ unsigned long long g_refbit[WORDS];   // ref-key occupancy (8MB)
__device__ unsigned long long g_state[NCHUNK];   // flag<<62 | rank<<21 | mask
__device__ int g_rankBase[WORDS];                // exclusive rank per word
__device__ int g_masked[1 << 20];                // ranks of masked outputs
__device__ int g_M;
__device__ int g_mTotal;
__device__ int g_cntS[8][FBLKMAX];               // per-(tap,block) counts
__device__ int g_listS[8][FBLKMAX][LCAP];        // per-(tap,block) input idx
__device__ int g_ovfl[8192];
__device__ int g_ovflCnt;

// ---- dedicated streaming zero fill ------------------------------------------
__global__ void __launch_bounds__(256) k_fill(float* __restrict__ out,
                                              long long startFloat,
                                              long long numFloats) {
    long long n4 = numFloats >> 2;
    float4* p = (float4*)(out + startFloat);
    float4 z = make_float4(0.f, 0.f, 0.f, 0.f);
    long long T = (long long)gridDim.x * blockDim.x;
    long long i = (long long)blockIdx.x * blockDim.x + threadIdx.x;
    for (; i + T < n4; i += 2 * T) {
        __stcs(&p[i], z);
        __stcs(&p[i + T], z);
    }
    if (i < n4) __stcs(&p[i], z);
    long long tail = numFloats & 3;
    if (blockIdx.x == 0 && threadIdx.x < tail)
        out[startFloat + (n4 << 2) + threadIdx.x] = 0.f;
}

// ---- ref bitmap + resets ------------------------------------------------------
__global__ void __launch_bounds__(256) k_ref(const int* __restrict__ rc, int NR) {
    int tid = blockIdx.x * blockDim.x + threadIdx.x;
    if (tid < NCHUNK) g_state[tid] = 0ull;
    if (tid == 0) g_ovflCnt = 0;
    if (tid >= NR) return;
    int4 c = ((const int4*)rc)[tid];
    int key = (c.x << 24) | (c.y << 16) | (c.z << 8) | c.w;
    atomicOr(&g_refbit[key >> 6], 1ull << (key & 63));
}

// ---- parent bitmap + per-(tap,block) contribution lists ----------------------
__global__ void __launch_bounds__(256) k_main(const int* __restrict__ coords, int N) {
    __shared__ int s_cnt[8];
    int tid = threadIdx.x, b = blockIdx.x;
    if (tid < 8) s_cnt[tid] = 0;
    __syncthreads();
    int base = b * FCH;
    const int4* c4 = (const int4*)coords;
#pragma unroll
    for (int r = 0; r < FCH / 256; r++) {
        int i = base + r * 256 + tid;
        if (i < N) {
            int4 c = c4[i];
            int key  = (c.x << 24) | (c.y << 16) | (c.z << 8) | c.w;
            int pkey = key & ~0x00010101;
            atomicOr(&g_bitmap[pkey >> 6], 1ull << (pkey & 63));
            if ((g_refbit[pkey >> 6] >> (pkey & 63)) & 1ull) {
                int tap = ((key >> 14) & 4) | ((key >> 7) & 2) | (key & 1);
                int lp = atomicAdd(&s_cnt[tap], 1);
                if (lp < LCAP) g_listS[tap][b][lp] = i;
                else {
                    int op = atomicAdd(&g_ovflCnt, 1);
                    if (op < 8192) g_ovfl[op] = (tap << 28) | i;
                }
            }
        }
    }
    __syncthreads();
    if (tid < 8) g_cntS[tid][b] = s_cnt[tid] < LCAP ? s_cnt[tid] : LCAP;
}

// ---- warp-shuffle dual scan + lookback: coords, rankBase, masked ranks -------
__global__ void __launch_bounds__(256) k_scanemit(float* __restrict__ out) {
    __shared__ unsigned long long s_wsum[8];
    __shared__ int s_exR, s_exM;
    const int tid  = threadIdx.x;
    const int lane = tid & 31;
    const int wid  = tid >> 5;
    const int b    = blockIdx.x;

    int base = b * CWORDS + tid * 4;
    unsigned long long w[4], mw[4];
    int s = 0, m = 0;
#pragma unroll
    for (int j = 0; j < 4; j++) {
        w[j]  = g_bitmap[base + j];
        mw[j] = w[j] & g_refbit[base + j];
        s += __popcll(w[j]);
        m += __popcll(mw[j]);
    }
    unsigned long long x = ((unsigned long long)s << 32) | (unsigned)m;
#pragma unroll
    for (int o = 1; o < 32; o <<= 1) {
        unsigned long long y = __shfl_up_sync(FULLM, x, o);
        if (lane >= o) x += y;
    }
    if (lane == 31) s_wsum[wid] = x;
    __syncthreads();
    if (wid == 0) {
        unsigned long long t = (lane < 8) ? s_wsum[lane] : 0ull;
#pragma unroll
        for (int o = 1; o < 8; o <<= 1) {
            unsigned long long y = __shfl_up_sync(FULLM, t, o);
            if (lane >= o) t += y;
        }
        if (lane < 8) s_wsum[lane] = t;
    }
    __syncthreads();
    unsigned long long incl = (wid ? s_wsum[wid - 1] : 0ull) + x;
    int thrExR = (int)(incl >> 32) - s;
    int thrExM = (int)(incl & 0xFFFFFFFFull) - m;
    int aggR = (int)(s_wsum[7] >> 32);
    int aggM = (int)(s_wsum[7] & 0xFFFFFFFFull);

    if (tid == 0) {
        long long exR = 0, exM = 0;
        if (b == 0) {
            atomicExch(&g_state[0], (2ull << 62) |
                       ((unsigned long long)aggR << 21) | (unsigned long long)aggM);
        } else {
            atomicExch(&g_state[b], (1ull << 62) |
                       ((unsigned long long)aggR << 21) | (unsigned long long)aggM);
            int j = b - 1;
            while (true) {
                unsigned long long v = *((volatile unsigned long long*)&g_state[j]);
                unsigned f = (unsigned)(v >> 62);
                if (f == 0) continue;
                exR += (long long)((v >> 21) & MASK21);
                exM += (long long)(v & MASK21);
                if (f == 2) break;
                j--;
            }
            atomicExch(&g_state[b], (2ull << 62) |
                       ((unsigned long long)(exR + aggR) << 21) |
                       (unsigned long long)(exM + aggM));
        }
        s_exR = (int)exR;
        s_exM = (int)exM;
        if (b == NCHUNK - 1) { g_M = (int)exR + aggR; g_mTotal = (int)exM + aggM; }
    }
    __syncthreads();

    int rank  = s_exR + thrExR;
    int mrank = s_exM + thrExM;
#pragma unroll
    for (int j = 0; j < 4; j++) {
        g_rankBase[base + j] = rank;
        unsigned long long ww = w[j], mm = mw[j];
        int keyhi = (base + j) << 6;
        while (ww) {
            int bpos = __ffsll((long long)ww) - 1;
            ww &= ww - 1;
            int k = keyhi | bpos;
            __stcs(&((float4*)out)[rank],
                   make_float4((float)(k >> 24), (float)((k >> 16) & 255),
                               (float)((k >> 8) & 255), (float)(k & 255)));
            if ((mm >> bpos) & 1ull) g_masked[mrank++] = rank;
            rank++;
        }
    }
}

// ---- tail: pad + mask/bias + tap-pinned conv (W registers loaded once) -------
__global__ void __launch_bounds__(256) k_biasconv(const float* __restrict__ feats,
                                                  const float* __restrict__ W,
                                                  const int* __restrict__ coords,
                                                  const float* __restrict__ bias,
                                                  float* __restrict__ out,
                                                  int N, int FBLK,
                                                  long long featBase,
                                                  long long maskBase) {
    const int lane = threadIdx.x & 31;
    const int gtid = blockIdx.x * blockDim.x + threadIdx.x;
    const int Tthr = gridDim.x * blockDim.x;
    const int gw   = gtid >> 5;
    const int totalWarps = Tthr >> 5;
    const int4* c4 = (const int4*)coords;

    // pad coords rows [M, N)
    int M = g_M;
    float4 neg1 = make_float4(-1.f, -1.f, -1.f, -1.f);
    for (int r = M + gtid; r < N; r += Tthr)
        __stcs(&((float4*)out)[r], neg1);

    // mask=1 + bias atomics for masked rows
    float b0 = __ldg(&bias[lane]);
    float b1 = __ldg(&bias[32 + lane]);
    int mc = g_mTotal;
    for (int i = gw; i < mc; i += totalWarps) {
        int r = g_masked[i];
        if (lane == 0) out[maskBase + r] = 1.0f;
        float* dst = out + featBase + (long long)r * 64;
        atomicAdd(dst + lane, b0);
        atomicAdd(dst + 32 + lane, b1);
    }

    // conv: warp pinned to one tap; W slice in regs loaded ONCE per warp
    int tap    = gw & 7;
    int sl0    = gw >> 3;
    int slstep = totalWarps >> 3;
    if (sl0 < FBLK) {
        float2 wreg[32];
        const float* Wt = W + tap * 2048;
#pragma unroll
        for (int j = 0; j < 32; j++)
            wreg[j] = make_float2(__ldg(&Wt[j * 64 + lane]),
                                  __ldg(&Wt[j * 64 + 32 + lane]));
        for (int slice = sl0; slice < FBLK; slice += slstep) {
            int cnt = g_cntS[tap][slice];
            for (int k = 0; k < cnt; k++) {
                int n = g_listS[tap][slice][k];
                int4 c = c4[n];
                int pkey = ((c.x << 24) | (c.y << 16) | (c.z << 8) | c.w) & ~0x00010101;
                int word = pkey >> 6, bit = pkey & 63;
                int rank = g_rankBase[word] +
                           __popcll(g_bitmap[word] & ((1ull << bit) - 1ull));
                float f = __ldg(&feats[(long long)n * 32 + lane]);
                float a0 = 0.f, a1 = 0.f;
#pragma unroll
                for (int j = 0; j < 32; j++) {
                    float fj = __shfl_sync(FULLM, f, j);
                    a0 += fj * wreg[j].x;
                    a1 += fj * wreg[j].y;
                }
                float* dst = out + featBase + (long long)rank * 64;
                atomicAdd(dst + lane, a0);
                atomicAdd(dst + 32 + lane, a1);
            }
        }
    }

    // overflow (expected empty)
    int oc = g_ovflCnt;
    for (int e = gw; e < oc && e < 8192; e += totalWarps) {
        int v = g_ovfl[e];
        int tp = v >> 28, n = v & 0x0FFFFFFF;
        int4 c = c4[n];
        int pkey = ((c.x << 24) | (c.y << 16) | (c.z << 8) | c.w) & ~0x00010101;
        int word = pkey >> 6, bit = pkey & 63;
        int rank = g_rankBase[word] +
                   __popcll(g_bitmap[word] & ((1ull << bit) - 1ull));
        float f = __ldg(&feats[(long long)n * 32 + lane]);
        float a0 = 0.f, a1 = 0.f;
        for (int j = 0; j < 32; j++) {
            float fj = __shfl_sync(FULLM, f, j);
            a0 += fj * __ldg(&W[tp * 2048 + j * 64 + lane]);
            a1 += fj * __ldg(&W[tp * 2048 + j * 64 + 32 + lane]);
        }
        float* dst = out + featBase + (long long)rank * 64;
        atomicAdd(dst + lane, a0);
        atomicAdd(dst + 32 + lane, a1);
    }
}

// ---- streams/events created at load time (no device-memory allocation) -----
static cudaStream_t g_sB;
static cudaEvent_t  g_evFork, g_evEmit;
namespace {
struct ResInit {
    ResInit() {
        cudaStreamCreateWithFlags(&g_sB, cudaStreamNonBlocking);
        cudaEventCreateWithFlags(&g_evFork, cudaEventDisableTiming);
        cudaEventCreateWithFlags(&g_evEmit, cudaEventDisableTiming);
    }
};
static ResInit g_resInit;
}

extern "C" void kernel_launch(void* const* d_in, const int* in_sizes, int n_in,
                              void* d_out, int out_size) {
    const float* feats  = (const float*)d_in[0];
    const float* W      = (const float*)d_in[1];
    const float* bias   = (const float*)d_in[2];
    const int*   coords = (const int*)d_in[3];
    const int*   ref    = (const int*)d_in[4];
    float* out = (float*)d_out;

    int N  = in_sizes[3] / 4;
    int NR = in_sizes[4] / 4;
    int FBLK = (N + FCH - 1) / FCH;
    long long featBase = 4LL * N;
    long long maskBase = (long long)out_size - N;          // == 68N
    long long zeroLen  = (long long)out_size - featBase;   // feats + mask (65N)

    cudaEventRecord(g_evFork, 0);
    cudaStreamWaitEvent(g_sB, g_evFork, 0);

    // s0: dedicated streaming fill (launch #0 per call -> ncu -s 5 hits
    //     this kernel on the second call)
    k_fill<<<592, 256, 0, 0>>>(out, featBase, zeroLen);

    // sB: ref -> main -> scanemit
    k_ref<<<(NR + 255) / 256, 256, 0, g_sB>>>(ref, NR);
    k_main<<<FBLK, 256, 0, g_sB>>>(coords, N);
    k_scanemit<<<NCHUNK, 256, 0, g_sB>>>(out);
    cudaEventRecord(g_evEmit, g_sB);

    // s0: join -> tail
    cudaStreamWaitEvent(0, g_evEmit, 0);
    k_biasconv<<<296, 256, 0, 0>>>(feats, W, coords, bias, out,
                                   N, FBLK, featBase, maskBase);
}

// round 13
// speedup vs baseline: 1.5743x; 1.1340x over previous
#include <cuda_runtime.h>
#include <stdint.h>

// ---------------------------------------------------------------------------
// DownsampleWithPruning — sparse stride-2 conv (2x2x2) + prune by ref set.
// Keyspace: b<<24 | x<<16 | y<<8 | z  in [0, 2^26)
//
// DAG (6 launches):
//   s0: k_fill     256MB feats zeros (dedicated streaming writer)
//   sB: k_ref      state reset + ref bitmap
//       k_bitA     parent bitmap OR
//       k_scan     dual lookback scan -> coords+mask (coalesced staged emit),
//                  rankBase (int4), masked-rank list
//       k_contrib  per-input: masked parent -> g_contrib[rank*8+tap]=i+1
//   s0: join -> k_tail  pad [M,N); warp-per-masked-row gather (bias + slots),
//                       plain float2 stores (no atomics)
// ---------------------------------------------------------------------------

#define WORDS   (1 << 20)       // 2^26 keys / 64
#define NCHUNK  1024            // scan chunks (1024 words each)
#define CWORDS  1024
#define MASK21  0x1FFFFFull
#define FULLM   0xffffffffu
#define SCAP    2048            // staged keys per chunk

__device__ unsigned long long g_bitmap[WORDS];   // parent-key occupancy (8MB)
__device__ unsigned long long g_refbit[WORDS];   // ref-key occupancy (8MB)
__device__ unsigned long long g_state[NCHUNK];   // flag<<62 | rank<<21 | mask
__device__ int g_rankBase[WORDS];                // global rank at word start
__device__ int g_masked[1 << 20];                // ranks of masked outputs
__device__ int g_contrib[8 * (1 << 20)];         // (rank,tap) -> input idx+1
__device__ int g_M;                              // unique outputs
__device__ int g_mTotal;                         // masked outputs

// ---- dedicated streaming zero fill (feats region only) ----------------------
__global__ void __launch_bounds__(256) k_fill(float* __restrict__ out,
                                              long long startFloat,
                                              long long numFloats) {
    long long n4 = numFloats >> 2;
    float4* p = (float4*)(out + startFloat);
    float4 z = make_float4(0.f, 0.f, 0.f, 0.f);
    long long T = (long long)gridDim.x * blockDim.x;
    long long i = (long long)blockIdx.x * blockDim.x + threadIdx.x;
    for (; i + T < n4; i += 2 * T) {
        __stcs(&p[i], z);
        __stcs(&p[i + T], z);
    }
    if (i < n4) __stcs(&p[i], z);
}

// ---- ref bitmap + state reset -------------------------------------------------
__global__ void __launch_bounds__(256) k_ref(const int* __restrict__ rc, int NR) {
    int tid = blockIdx.x * blockDim.x + threadIdx.x;
    if (tid < NCHUNK) g_state[tid] = 0ull;
    if (tid >= NR) return;
    int4 c = ((const int4*)rc)[tid];
    int key = (c.x << 24) | (c.y << 16) | (c.z << 8) | c.w;
    atomicOr(&g_refbit[key >> 6], 1ull << (key & 63));
}

// ---- parent bitmap ------------------------------------------------------------
__global__ void __launch_bounds__(256) k_bitA(const int* __restrict__ coords, int N) {
    int tid = blockIdx.x * blockDim.x + threadIdx.x;
    int T = gridDim.x * blockDim.x;
    const int4* c4 = (const int4*)coords;
#pragma unroll 4
    for (int i = tid; i < N; i += T) {
        int4 c = c4[i];
        int pkey = ((c.x << 24) | (c.y << 16) | (c.z << 8) | c.w) & ~0x00010101;
        atomicOr(&g_bitmap[pkey >> 6], 1ull << (pkey & 63));
    }
}

// ---- dual lookback scan; staged coalesced emit of coords + mask ---------------
__global__ void __launch_bounds__(256) k_scan(float* __restrict__ out,
                                              long long maskBase) {
    __shared__ unsigned long long s_wsum[8];
    __shared__ int s_exR, s_exM;
    __shared__ int s_keys[SCAP];
    const int tid  = threadIdx.x;
    const int lane = tid & 31;
    const int wid  = tid >> 5;
    const int b    = blockIdx.x;

    int base = b * CWORDS + tid * 4;
    unsigned long long w[4], mw[4];
    int s = 0, m = 0;
#pragma unroll
    for (int j = 0; j < 4; j++) {
        w[j]  = g_bitmap[base + j];
        mw[j] = w[j] & g_refbit[base + j];
        s += __popcll(w[j]);
        m += __popcll(mw[j]);
    }
    unsigned long long x = ((unsigned long long)s << 32) | (unsigned)m;
#pragma unroll
    for (int o = 1; o < 32; o <<= 1) {
        unsigned long long y = __shfl_up_sync(FULLM, x, o);
        if (lane >= o) x += y;
    }
    if (lane == 31) s_wsum[wid] = x;
    __syncthreads();
    if (wid == 0) {
        unsigned long long t = (lane < 8) ? s_wsum[lane] : 0ull;
#pragma unroll
        for (int o = 1; o < 8; o <<= 1) {
            unsigned long long y = __shfl_up_sync(FULLM, t, o);
            if (lane >= o) t += y;
        }
        if (lane < 8) s_wsum[lane] = t;
    }
    __syncthreads();
    unsigned long long incl = (wid ? s_wsum[wid - 1] : 0ull) + x;
    int thrExR = (int)(incl >> 32) - s;               // block-local
    int thrExM = (int)(incl & 0xFFFFFFFFull) - m;
    int aggR = (int)(s_wsum[7] >> 32);
    int aggM = (int)(s_wsum[7] & 0xFFFFFFFFull);

    if (tid == 0) {
        long long exR = 0, exM = 0;
        if (b == 0) {
            atomicExch(&g_state[0], (2ull << 62) |
                       ((unsigned long long)aggR << 21) | (unsigned long long)aggM);
        } else {
            atomicExch(&g_state[b], (1ull << 62) |
                       ((unsigned long long)aggR << 21) | (unsigned long long)aggM);
            int j = b - 1;
            while (true) {
                unsigned long long v = *((volatile unsigned long long*)&g_state[j]);
                unsigned f = (unsigned)(v >> 62);
                if (f == 0) continue;
                exR += (long long)((v >> 21) & MASK21);
                exM += (long long)(v & MASK21);
                if (f == 2) break;
                j--;
            }
            atomicExch(&g_state[b], (2ull << 62) |
                       ((unsigned long long)(exR + aggR) << 21) |
                       (unsigned long long)(exM + aggM));
        }
        s_exR = (int)exR;
        s_exM = (int)exM;
        if (b == NCHUNK - 1) { g_M = (int)exR + aggR; g_mTotal = (int)exM + aggM; }
    }
    __syncthreads();

    bool useStage = (aggR <= SCAP);
    int exR = s_exR;
    int lrank = thrExR;                               // block-local rank
    int mrank = s_exM + thrExM;                       // global masked index
    int rb[4];
#pragma unroll
    for (int j = 0; j < 4; j++) {
        rb[j] = exR + lrank;
        unsigned long long ww = w[j], mm = mw[j];
        int keyhi = (base + j) << 6;
        while (ww) {
            int bpos = __ffsll((long long)ww) - 1;
            ww &= ww - 1;
            int k = keyhi | bpos;
            bool msk = (mm >> bpos) & 1ull;
            if (useStage) {
                s_keys[lrank] = k | (msk ? 0x80000000 : 0);
            } else {
                __stcs(&((float4*)out)[exR + lrank],
                       make_float4((float)(k >> 24), (float)((k >> 16) & 255),
                                   (float)((k >> 8) & 255), (float)(k & 255)));
                __stcs(&out[maskBase + exR + lrank], msk ? 1.0f : 0.0f);
            }
            if (msk) g_masked[mrank++] = exR + lrank;
            lrank++;
        }
    }
    *((int4*)&g_rankBase[base]) = make_int4(rb[0], rb[1], rb[2], rb[3]);

    if (useStage) {
        __syncthreads();
        for (int idx = tid; idx < aggR; idx += 256) {
            int kk = s_keys[idx];
            int k = kk & 0x03FFFFFF;
            __stcs(&((float4*)out)[exR + idx],
                   make_float4((float)(k >> 24), (float)((k >> 16) & 255),
                               (float)((k >> 8) & 255), (float)(k & 255)));
            __stcs(&out[maskBase + exR + idx],
                   ((unsigned)kk >> 31) ? 1.0f : 0.0f);
        }
    }
}

// ---- contributions: input -> (parent rank, tap) slot ---------------------------
__global__ void __launch_bounds__(256) k_contrib(const int* __restrict__ coords, int N) {
    int tid = blockIdx.x * blockDim.x + threadIdx.x;
    int T = gridDim.x * blockDim.x;
    const int4* c4 = (const int4*)coords;
    for (int i = tid; i < N; i += T) {
        int4 c = c4[i];
        int key  = (c.x << 24) | (c.y << 16) | (c.z << 8) | c.w;
        int pkey = key & ~0x00010101;
        int word = pkey >> 6, bit = pkey & 63;
        if ((g_refbit[word] >> bit) & 1ull) {
            int rank = g_rankBase[word] +
                       __popcll(g_bitmap[word] & ((1ull << bit) - 1ull));
            int tap = ((key >> 14) & 4) | ((key >> 7) & 2) | (key & 1);
            g_contrib[rank * 8 + tap] = i + 1;       // unique writer per slot
        }
    }
}

// ---- tail: pad [M,N) + warp-per-masked-row gather (plain stores) --------------
__global__ void __launch_bounds__(256) k_tail(const float* __restrict__ feats,
                                              const float* __restrict__ W,
                                              const float* __restrict__ bias,
                                              float* __restrict__ out,
                                              int N,
                                              long long featBase,
                                              long long maskBase) {
    const int lane = threadIdx.x & 31;
    const int gtid = blockIdx.x * blockDim.x + threadIdx.x;
    const int Tthr = gridDim.x * blockDim.x;
    const int gw   = gtid >> 5;
    const int totalWarps = Tthr >> 5;

    // pad coords + mask rows [M, N)
    int M = g_M;
    float4 neg1 = make_float4(-1.f, -1.f, -1.f, -1.f);
    for (int r = M + gtid; r < N; r += Tthr) {
        __stcs(&((float4*)out)[r], neg1);
        __stcs(&out[maskBase + r], 0.0f);
    }

    float2 bv = ((const float2*)bias)[lane];
    int mc = g_mTotal;
    for (int i = gw; i < mc; i += totalWarps) {
        int r = g_masked[i];
        int v = (lane < 8) ? g_contrib[r * 8 + lane] : 0;
        unsigned act = __ballot_sync(FULLM, v != 0) & 0xFFu;
        float2 acc = bv;
        while (act) {
            int t = __ffs(act) - 1;
            act &= act - 1;
            int n = __shfl_sync(FULLM, v, t) - 1;
            float f = __ldg(&feats[(long long)n * 32 + lane]);
            const float2* Wt = (const float2*)(W + t * 2048);
#pragma unroll
            for (int j = 0; j < 32; j++) {
                float fj = __shfl_sync(FULLM, f, j);
                float2 wv = __ldg(&Wt[j * 32 + lane]);
                acc.x += fj * wv.x;
                acc.y += fj * wv.y;
            }
        }
        ((float2*)(out + featBase + (long long)r * 64))[lane] = acc;
    }
}

// ---- streams/events created at load time (no device-memory allocation) -----
static cudaStream_t g_sB;
static cudaEvent_t  g_evFork, g_evEmit;
namespace {
struct ResInit {
    ResInit() {
        cudaStreamCreateWithFlags(&g_sB, cudaStreamNonBlocking);
        cudaEventCreateWithFlags(&g_evFork, cudaEventDisableTiming);
        cudaEventCreateWithFlags(&g_evEmit, cudaEventDisableTiming);
    }
};
static ResInit g_resInit;
}

extern "C" void kernel_launch(void* const* d_in, const int* in_sizes, int n_in,
                              void* d_out, int out_size) {
    const float* feats  = (const float*)d_in[0];
    const float* W      = (const float*)d_in[1];
    const float* bias   = (const float*)d_in[2];
    const int*   coords = (const int*)d_in[3];
    const int*   ref    = (const int*)d_in[4];
    float* out = (float*)d_out;

    int N  = in_sizes[3] / 4;
    int NR = in_sizes[4] / 4;
    long long featBase = 4LL * N;
    long long maskBase = (long long)out_size - N;   // == 68N
    long long featLen  = 64LL * N;                  // feats region only

    cudaEventRecord(g_evFork, 0);
    cudaStreamWaitEvent(g_sB, g_evFork, 0);

    // s0: dedicated streaming fill of feats
    k_fill<<<592, 256, 0, 0>>>(out, featBase, featLen);

    // sB: ref -> bitA -> scan -> contrib
    k_ref<<<(NR + 255) / 256, 256, 0, g_sB>>>(ref, NR);
    k_bitA<<<1184, 256, 0, g_sB>>>(coords, N);
    k_scan<<<NCHUNK, 256, 0, g_sB>>>(out, maskBase);
    k_contrib<<<1184, 256, 0, g_sB>>>(coords, N);
    cudaEventRecord(g_evEmit, g_sB);

    // s0: join -> gather tail
    cudaStreamWaitEvent(0, g_evEmit, 0);
    k_tail<<<1184, 256, 0, 0>>>(feats, W, bias, out, N, featBase, maskBase);
}

// round 14
// speedup vs baseline: 1.6267x; 1.0333x over previous
#include <cuda_runtime.h>
#include <stdint.h>

// ---------------------------------------------------------------------------
// DownsampleWithPruning — sparse stride-2 conv (2x2x2) + prune by ref set.
// Keyspace: b<<24 | x<<16 | y<<8 | z  in [0, 2^26)
//
// DAG (6 launches):
//   s0: k_fill     256MB feats zeros (888 blocks, streaming __stcs)
//   sB: k_ref      state reset + ref bitmap
//       k_bitA     parent bitmap OR + packed key emit (coords read ONCE)
//       k_scan     dual lookback scan (warp-parallel lookback) ->
//                  coords+mask staged emit, rankBase, masked-rank list
//       k_contrib  g_keys -> g_contrib[rank*8+tap]=i+1 (unique writer)
//   s0: join -> k_tail  pad [M,N); warp-per-masked-row gather, plain stores
// ---------------------------------------------------------------------------

#define WORDS   (1 << 20)       // 2^26 keys / 64
#define NCHUNK  1024            // scan chunks (1024 words each)
#define CWORDS  1024
#define MASK21  0x1FFFFFull
#define FULLM   0xffffffffu
#define SCAP    2048            // staged keys per chunk

__device__ unsigned long long g_bitmap[WORDS];   // parent-key occupancy (8MB)
__device__ unsigned long long g_refbit[WORDS];   // ref-key occupancy (8MB)
__device__ unsigned long long g_state[NCHUNK];   // flag<<62 | rank<<21 | mask
__device__ int g_rankBase[WORDS];                // global rank at word start
__device__ int g_keys[1 << 20];                  // packed input keys (4MB)
__device__ int g_masked[1 << 20];                // ranks of masked outputs
__device__ int g_contrib[8 * (1 << 20)];         // (rank,tap) -> input idx+1
__device__ int g_M;                              // unique outputs
__device__ int g_mTotal;                         // masked outputs

// ---- dedicated streaming zero fill (feats region only) ----------------------
__global__ void __launch_bounds__(256) k_fill(float* __restrict__ out,
                                              long long startFloat,
                                              long long numFloats) {
    long long n4 = numFloats >> 2;
    float4* p = (float4*)(out + startFloat);
    float4 z = make_float4(0.f, 0.f, 0.f, 0.f);
    long long T = (long long)gridDim.x * blockDim.x;
    long long i = (long long)blockIdx.x * blockDim.x + threadIdx.x;
    for (; i + T < n4; i += 2 * T) {
        __stcs(&p[i], z);
        __stcs(&p[i + T], z);
    }
    if (i < n4) __stcs(&p[i], z);
}

// ---- ref bitmap + state reset -------------------------------------------------
__global__ void __launch_bounds__(256) k_ref(const int* __restrict__ rc, int NR) {
    int tid = blockIdx.x * blockDim.x + threadIdx.x;
    if (tid < NCHUNK) g_state[tid] = 0ull;
    if (tid >= NR) return;
    int4 c = ((const int4*)rc)[tid];
    int key = (c.x << 24) | (c.y << 16) | (c.z << 8) | c.w;
    atomicOr(&g_refbit[key >> 6], 1ull << (key & 63));
}

// ---- parent bitmap + packed key emit (coords read once) ------------------------
__global__ void __launch_bounds__(256) k_bitA(const int* __restrict__ coords, int N) {
    int tid = blockIdx.x * blockDim.x + threadIdx.x;
    int T = gridDim.x * blockDim.x;
    const int4* c4 = (const int4*)coords;
#pragma unroll 4
    for (int i = tid; i < N; i += T) {
        int4 c = c4[i];
        int key = (c.x << 24) | (c.y << 16) | (c.z << 8) | c.w;
        g_keys[i] = key;
        int pkey = key & ~0x00010101;
        atomicOr(&g_bitmap[pkey >> 6], 1ull << (pkey & 63));
    }
}

// ---- dual lookback scan (warp-parallel lookback); staged coalesced emit -------
__global__ void __launch_bounds__(256) k_scan(float* __restrict__ out,
                                              long long maskBase) {
    __shared__ unsigned long long s_wsum[8];
    __shared__ int s_exR, s_exM;
    __shared__ int s_keys[SCAP];
    const int tid  = threadIdx.x;
    const int lane = tid & 31;
    const int wid  = tid >> 5;
    const int b    = blockIdx.x;

    int base = b * CWORDS + tid * 4;
    unsigned long long w[4], mw[4];
    int s = 0, m = 0;
#pragma unroll
    for (int j = 0; j < 4; j++) {
        w[j]  = g_bitmap[base + j];
        mw[j] = w[j] & g_refbit[base + j];
        s += __popcll(w[j]);
        m += __popcll(mw[j]);
    }
    unsigned long long x = ((unsigned long long)s << 32) | (unsigned)m;
#pragma unroll
    for (int o = 1; o < 32; o <<= 1) {
        unsigned long long y = __shfl_up_sync(FULLM, x, o);
        if (lane >= o) x += y;
    }
    if (lane == 31) s_wsum[wid] = x;
    __syncthreads();
    if (wid == 0) {
        unsigned long long t = (lane < 8) ? s_wsum[lane] : 0ull;
#pragma unroll
        for (int o = 1; o < 8; o <<= 1) {
            unsigned long long y = __shfl_up_sync(FULLM, t, o);
            if (lane >= o) t += y;
        }
        if (lane < 8) s_wsum[lane] = t;
    }
    __syncthreads();
    unsigned long long incl = (wid ? s_wsum[wid - 1] : 0ull) + x;
    int thrExR = (int)(incl >> 32) - s;               // block-local
    int thrExM = (int)(incl & 0xFFFFFFFFull) - m;
    int aggR = (int)(s_wsum[7] >> 32);
    int aggM = (int)(s_wsum[7] & 0xFFFFFFFFull);

    // warp 0: warp-parallel decoupled lookback
    if (wid == 0) {
        long long exR = 0, exM = 0;
        if (b == 0) {
            if (lane == 0)
                atomicExch(&g_state[0], (2ull << 62) |
                           ((unsigned long long)aggR << 21) |
                           (unsigned long long)aggM);
        } else {
            if (lane == 0)
                atomicExch(&g_state[b], (1ull << 62) |
                           ((unsigned long long)aggR << 21) |
                           (unsigned long long)aggM);
            int j = b - 1;
            while (true) {
                int idx = j - lane;
                unsigned long long v = (idx >= 0)
                    ? *((volatile unsigned long long*)&g_state[idx])
                    : (2ull << 62);                   // virtual flag2, value 0
                unsigned f = (unsigned)(v >> 62);
                unsigned b2 = __ballot_sync(FULLM, f == 2);
                unsigned b0 = __ballot_sync(FULLM, f == 0);
                int f2 = b2 ? (__ffs(b2) - 1) : 32;
                int f0 = b0 ? (__ffs(b0) - 1) : 32;
                if (f0 < f2) continue;                // not ready: retry window
                int rv = 0, mv = 0;
                if (lane <= f2) {
                    rv = (int)((v >> 21) & MASK21);
                    mv = (int)(v & MASK21);
                }
#pragma unroll
                for (int o = 16; o; o >>= 1) {
                    rv += __shfl_down_sync(FULLM, rv, o);
                    mv += __shfl_down_sync(FULLM, mv, o);
                }
                rv = __shfl_sync(FULLM, rv, 0);
                mv = __shfl_sync(FULLM, mv, 0);
                exR += rv; exM += mv;
                if (f2 < 32) break;
                j -= 32;
            }
            if (lane == 0)
                atomicExch(&g_state[b], (2ull << 62) |
                           ((unsigned long long)(exR + aggR) << 21) |
                           (unsigned long long)(exM + aggM));
        }
        if (lane == 0) {
            s_exR = (int)exR;
            s_exM = (int)exM;
            if (b == NCHUNK - 1) { g_M = (int)exR + aggR; g_mTotal = (int)exM + aggM; }
        }
    }
    __syncthreads();

    bool useStage = (aggR <= SCAP);
    int exR = s_exR;
    int lrank = thrExR;                               // block-local rank
    int mrank = s_exM + thrExM;                       // global masked index
    int rb[4];
#pragma unroll
    for (int j = 0; j < 4; j++) {
        rb[j] = exR + lrank;
        unsigned long long ww = w[j], mm = mw[j];
        int keyhi = (base + j) << 6;
        while (ww) {
            int bpos = __ffsll((long long)ww) - 1;
            ww &= ww - 1;
            int k = keyhi | bpos;
            bool msk = (mm >> bpos) & 1ull;
            if (useStage) {
                s_keys[lrank] = k | (msk ? 0x80000000 : 0);
            } else {
                __stcs(&((float4*)out)[exR + lrank],
                       make_float4((float)(k >> 24), (float)((k >> 16) & 255),
                                   (float)((k >> 8) & 255), (float)(k & 255)));
                __stcs(&out[maskBase + exR + lrank], msk ? 1.0f : 0.0f);
            }
            if (msk) g_masked[mrank++] = exR + lrank;
            lrank++;
        }
    }
    *((int4*)&g_rankBase[base]) = make_int4(rb[0], rb[1], rb[2], rb[3]);

    if (useStage) {
        __syncthreads();
        for (int idx = tid; idx < aggR; idx += 256) {
            int kk = s_keys[idx];
            int k = kk & 0x03FFFFFF;
            __stcs(&((float4*)out)[exR + idx],
                   make_float4((float)(k >> 24), (float)((k >> 16) & 255),
                               (float)((k >> 8) & 255), (float)(k & 255)));
            __stcs(&out[maskBase + exR + idx],
                   ((unsigned)kk >> 31) ? 1.0f : 0.0f);
        }
    }
}

// ---- contributions: packed keys -> (parent rank, tap) slot ---------------------
__global__ void __launch_bounds__(256) k_contrib(int N) {
    int tid = blockIdx.x * blockDim.x + threadIdx.x;
    int T = gridDim.x * blockDim.x;
    for (int i = tid; i < N; i += T) {
        int key  = g_keys[i];
        int pkey = key & ~0x00010101;
        int word = pkey >> 6, bit = pkey & 63;
        if ((g_refbit[word] >> bit) & 1ull) {
            int rank = g_rankBase[word] +
                       __popcll(g_bitmap[word] & ((1ull << bit) - 1ull));
            int tap = ((key >> 14) & 4) | ((key >> 7) & 2) | (key & 1);
            g_contrib[rank * 8 + tap] = i + 1;       // unique writer per slot
        }
    }
}

// ---- tail: pad [M,N) + warp-per-masked-row gather (plain stores) --------------
__global__ void __launch_bounds__(256) k_tail(const float* __restrict__ feats,
                                              const float* __restrict__ W,
                                              const float* __restrict__ bias,
                                              float* __restrict__ out,
                                              int N,
                                              long long featBase,
                                              long long maskBase) {
    const int lane = threadIdx.x & 31;
    const int gtid = blockIdx.x * blockDim.x + threadIdx.x;
    const int Tthr = gridDim.x * blockDim.x;
    const int gw   = gtid >> 5;
    const int totalWarps = Tthr >> 5;

    // pad coords + mask rows [M, N)
    int M = g_M;
    float4 neg1 = make_float4(-1.f, -1.f, -1.f, -1.f);
    for (int r = M + gtid; r < N; r += Tthr) {
        __stcs(&((float4*)out)[r], neg1);
        __stcs(&out[maskBase + r], 0.0f);
    }

    float2 bv = ((const float2*)bias)[lane];
    int mc = g_mTotal;
    for (int i = gw; i < mc; i += totalWarps) {
        int r = g_masked[i];
        int v = (lane < 8) ? g_contrib[r * 8 + lane] : 0;
        unsigned act = __ballot_sync(FULLM, v != 0) & 0xFFu;
        float2 acc = bv;
        while (act) {
            int t = __ffs(act) - 1;
            act &= act - 1;
            int n = __shfl_sync(FULLM, v, t) - 1;
            float f = __ldg(&feats[(long long)n * 32 + lane]);
            const float2* Wt = (const float2*)(W + t * 2048);
#pragma unroll
            for (int j = 0; j < 32; j++) {
                float fj = __shfl_sync(FULLM, f, j);
                float2 wv = __ldg(&Wt[j * 32 + lane]);
                acc.x += fj * wv.x;
                acc.y += fj * wv.y;
            }
        }
        ((float2*)(out + featBase + (long long)r * 64))[lane] = acc;
    }
}

// ---- streams/events created at load time (no device-memory allocation) -----
static cudaStream_t g_sB;
static cudaEvent_t  g_evFork, g_evEmit;
namespace {
struct ResInit {
    ResInit() {
        cudaStreamCreateWithFlags(&g_sB, cudaStreamNonBlocking);
        cudaEventCreateWithFlags(&g_evFork, cudaEventDisableTiming);
        cudaEventCreateWithFlags(&g_evEmit, cudaEventDisableTiming);
    }
};
static ResInit g_resInit;
}

extern "C" void kernel_launch(void* const* d_in, const int* in_sizes, int n_in,
                              void* d_out, int out_size) {
    const float* feats  = (const float*)d_in[0];
    const float* W      = (const float*)d_in[1];
    const float* bias   = (const float*)d_in[2];
    const int*   coords = (const int*)d_in[3];
    const int*   ref    = (const int*)d_in[4];
    float* out = (float*)d_out;

    int N  = in_sizes[3] / 4;
    int NR = in_sizes[4] / 4;
    long long featBase = 4LL * N;
    long long maskBase = (long long)out_size - N;   // == 68N
    long long featLen  = 64LL * N;                  // feats region only

    cudaEventRecord(g_evFork, 0);
    cudaStreamWaitEvent(g_sB, g_evFork, 0);

    // s0: dedicated streaming fill of feats (6 blocks/SM)
    k_fill<<<888, 256, 0, 0>>>(out, featBase, featLen);

    // sB: ref -> bitA (keys) -> scan -> contrib
    k_ref<<<(NR + 255) / 256, 256, 0, g_sB>>>(ref, NR);
    k_bitA<<<1184, 256, 0, g_sB>>>(coords, N);
    k_scan<<<NCHUNK, 256, 0, g_sB>>>(out, maskBase);
    k_contrib<<<1184, 256, 0, g_sB>>>(N);
    cudaEventRecord(g_evEmit, g_sB);

    // s0: join -> gather tail
    cudaStreamWaitEvent(0, g_evEmit, 0);
    k_tail<<<1184, 256, 0, 0>>>(feats, W, bias, out, N, featBase, maskBase);
}

// round 15
// speedup vs baseline: 1.6543x; 1.0169x over previous
#include <cuda_runtime.h>
#include <stdint.h>

// ---------------------------------------------------------------------------
// DownsampleWithPruning — sparse stride-2 conv (2x2x2) + prune by ref set.
// Keyspace: b<<24 | x<<16 | y<<8 | z  in [0, 2^26)
//
// DAG (5 nodes):
//   s0: memsetAsync  256MB feats zeros (driver fill path — A/B vs kernel fill)
//   sB: k_setup      state reset + ref bitmap + packed keys + parent bitmap
//       k_scan       dual lookback scan (warp-parallel lookback) ->
//                    coords+mask staged emit, rankBase, masked-rank list
//       k_contrib    g_keys -> g_contrib[rank*8+tap]=i+1 (unique writer)
//   s0: join -> k_tail  pad [M,N); warp-per-masked-row gather, plain stores
// ---------------------------------------------------------------------------

#define WORDS   (1 << 20)       // 2^26 keys / 64
#define NCHUNK  1024            // scan chunks (1024 words each)
#define CWORDS  1024
#define MASK21  0x1FFFFFull
#define FULLM   0xffffffffu
#define SCAP    2048            // staged keys per chunk

__device__ unsigned long long g_bitmap[WORDS];   // parent-key occupancy (8MB)
__device__ unsigned long long g_refbit[WORDS];   // ref-key occupancy (8MB)
__device__ unsigned long long g_state[NCHUNK];   // flag<<62 | rank<<21 | mask
__device__ int g_rankBase[WORDS];                // global rank at word start
__device__ int g_keys[1 << 20];                  // packed input keys (4MB)
__device__ int g_masked[1 << 20];                // ranks of masked outputs
__device__ int g_contrib[8 * (1 << 20)];         // (rank,tap) -> input idx+1
__device__ int g_M;                              // unique outputs
__device__ int g_mTotal;                         // masked outputs

// ---- setup: state reset + ref bitmap + keys + parent bitmap ------------------
__global__ void __launch_bounds__(256) k_setup(const int* __restrict__ coords, int N,
                                               const int* __restrict__ rc, int NR) {
    int tid = blockIdx.x * blockDim.x + threadIdx.x;
    int T = gridDim.x * blockDim.x;
    if (tid < NCHUNK) g_state[tid] = 0ull;

    const int4* rc4 = (const int4*)rc;
#pragma unroll 2
    for (int i = tid; i < NR; i += T) {
        int4 c = rc4[i];
        int key = (c.x << 24) | (c.y << 16) | (c.z << 8) | c.w;
        atomicOr(&g_refbit[key >> 6], 1ull << (key & 63));
    }
    const int4* c4 = (const int4*)coords;
#pragma unroll 2
    for (int i = tid; i < N; i += T) {
        int4 c = c4[i];
        int key = (c.x << 24) | (c.y << 16) | (c.z << 8) | c.w;
        g_keys[i] = key;
        int pkey = key & ~0x00010101;
        atomicOr(&g_bitmap[pkey >> 6], 1ull << (pkey & 63));
    }
}

// ---- dual lookback scan (warp-parallel lookback); staged coalesced emit -------
__global__ void __launch_bounds__(256) k_scan(float* __restrict__ out,
                                              long long maskBase) {
    __shared__ unsigned long long s_wsum[8];
    __shared__ int s_exR, s_exM;
    __shared__ int s_keys[SCAP];
    const int tid  = threadIdx.x;
    const int lane = tid & 31;
    const int wid  = tid >> 5;
    const int b    = blockIdx.x;

    int base = b * CWORDS + tid * 4;
    unsigned long long w[4], mw[4];
    int s = 0, m = 0;
#pragma unroll
    for (int j = 0; j < 4; j++) {
        w[j]  = g_bitmap[base + j];
        mw[j] = w[j] & g_refbit[base + j];
        s += __popcll(w[j]);
        m += __popcll(mw[j]);
    }
    unsigned long long x = ((unsigned long long)s << 32) | (unsigned)m;
#pragma unroll
    for (int o = 1; o < 32; o <<= 1) {
        unsigned long long y = __shfl_up_sync(FULLM, x, o);
        if (lane >= o) x += y;
    }
    if (lane == 31) s_wsum[wid] = x;
    __syncthreads();
    if (wid == 0) {
        unsigned long long t = (lane < 8) ? s_wsum[lane] : 0ull;
#pragma unroll
        for (int o = 1; o < 8; o <<= 1) {
            unsigned long long y = __shfl_up_sync(FULLM, t, o);
            if (lane >= o) t += y;
        }
        if (lane < 8) s_wsum[lane] = t;
    }
    __syncthreads();
    unsigned long long incl = (wid ? s_wsum[wid - 1] : 0ull) + x;
    int thrExR = (int)(incl >> 32) - s;               // block-local
    int thrExM = (int)(incl & 0xFFFFFFFFull) - m;
    int aggR = (int)(s_wsum[7] >> 32);
    int aggM = (int)(s_wsum[7] & 0xFFFFFFFFull);

    // warp 0: warp-parallel decoupled lookback
    if (wid == 0) {
        long long exR = 0, exM = 0;
        if (b == 0) {
            if (lane == 0)
                atomicExch(&g_state[0], (2ull << 62) |
                           ((unsigned long long)aggR << 21) |
                           (unsigned long long)aggM);
        } else {
            if (lane == 0)
                atomicExch(&g_state[b], (1ull << 62) |
                           ((unsigned long long)aggR << 21) |
                           (unsigned long long)aggM);
            int j = b - 1;
            while (true) {
                int idx = j - lane;
                unsigned long long v = (idx >= 0)
                    ? *((volatile unsigned long long*)&g_state[idx])
                    : (2ull << 62);                   // virtual flag2, value 0
                unsigned f = (unsigned)(v >> 62);
                unsigned b2 = __ballot_sync(FULLM, f == 2);
                unsigned b0 = __ballot_sync(FULLM, f == 0);
                int f2 = b2 ? (__ffs(b2) - 1) : 32;
                int f0 = b0 ? (__ffs(b0) - 1) : 32;
                if (f0 < f2) continue;                // not ready: retry window
                int rv = 0, mv = 0;
                if (lane <= f2) {
                    rv = (int)((v >> 21) & MASK21);
                    mv = (int)(v & MASK21);
                }
#pragma unroll
                for (int o = 16; o; o >>= 1) {
                    rv += __shfl_down_sync(FULLM, rv, o);
                    mv += __shfl_down_sync(FULLM, mv, o);
                }
                rv = __shfl_sync(FULLM, rv, 0);
                mv = __shfl_sync(FULLM, mv, 0);
                exR += rv; exM += mv;
                if (f2 < 32) break;
                j -= 32;
            }
            if (lane == 0)
                atomicExch(&g_state[b], (2ull << 62) |
                           ((unsigned long long)(exR + aggR) << 21) |
                           (unsigned long long)(exM + aggM));
        }
        if (lane == 0) {
            s_exR = (int)exR;
            s_exM = (int)exM;
            if (b == NCHUNK - 1) { g_M = (int)exR + aggR; g_mTotal = (int)exM + aggM; }
        }
    }
    __syncthreads();

    bool useStage = (aggR <= SCAP);
    int exR = s_exR;
    int lrank = thrExR;                               // block-local rank
    int mrank = s_exM + thrExM;                       // global masked index
    int rb[4];
#pragma unroll
    for (int j = 0; j < 4; j++) {
        rb[j] = exR + lrank;
        unsigned long long ww = w[j], mm = mw[j];
        int keyhi = (base + j) << 6;
        while (ww) {
            int bpos = __ffsll((long long)ww) - 1;
            ww &= ww - 1;
            int k = keyhi | bpos;
            bool msk = (mm >> bpos) & 1ull;
            if (useStage) {
                s_keys[lrank] = k | (msk ? 0x80000000 : 0);
            } else {
                __stcs(&((float4*)out)[exR + lrank],
                       make_float4((float)(k >> 24), (float)((k >> 16) & 255),
                                   (float)((k >> 8) & 255), (float)(k & 255)));
                __stcs(&out[maskBase + exR + lrank], msk ? 1.0f : 0.0f);
            }
            if (msk) g_masked[mrank++] = exR + lrank;
            lrank++;
        }
    }
    *((int4*)&g_rankBase[base]) = make_int4(rb[0], rb[1], rb[2], rb[3]);

    if (useStage) {
        __syncthreads();
        for (int idx = tid; idx < aggR; idx += 256) {
            int kk = s_keys[idx];
            int k = kk & 0x03FFFFFF;
            __stcs(&((float4*)out)[exR + idx],
                   make_float4((float)(k >> 24), (float)((k >> 16) & 255),
                               (float)((k >> 8) & 255), (float)(k & 255)));
            __stcs(&out[maskBase + exR + idx],
                   ((unsigned)kk >> 31) ? 1.0f : 0.0f);
        }
    }
}

// ---- contributions: packed keys -> (parent rank, tap) slot ---------------------
__global__ void __launch_bounds__(256) k_contrib(int N) {
    int tid = blockIdx.x * blockDim.x + threadIdx.x;
    int T = gridDim.x * blockDim.x;
    for (int i = tid; i < N; i += T) {
        int key  = g_keys[i];
        int pkey = key & ~0x00010101;
        int word = pkey >> 6, bit = pkey & 63;
        if ((g_refbit[word] >> bit) & 1ull) {
            int rank = g_rankBase[word] +
                       __popcll(g_bitmap[word] & ((1ull << bit) - 1ull));
            int tap = ((key >> 14) & 4) | ((key >> 7) & 2) | (key & 1);
            g_contrib[rank * 8 + tap] = i + 1;       // unique writer per slot
        }
    }
}

// ---- tail: pad [M,N) + warp-per-masked-row gather (plain stores) --------------
__global__ void __launch_bounds__(256) k_tail(const float* __restrict__ feats,
                                              const float* __restrict__ W,
                                              const float* __restrict__ bias,
                                              float* __restrict__ out,
                                              int N,
                                              long long featBase,
                                              long long maskBase) {
    const int lane = threadIdx.x & 31;
    const int gtid = blockIdx.x * blockDim.x + threadIdx.x;
    const int Tthr = gridDim.x * blockDim.x;
    const int gw   = gtid >> 5;
    const int totalWarps = Tthr >> 5;

    // pad coords + mask rows [M, N)
    int M = g_M;
    float4 neg1 = make_float4(-1.f, -1.f, -1.f, -1.f);
    for (int r = M + gtid; r < N; r += Tthr) {
        __stcs(&((float4*)out)[r], neg1);
        __stcs(&out[maskBase + r], 0.0f);
    }

    float2 bv = ((const float2*)bias)[lane];
    int mc = g_mTotal;
    for (int i = gw; i < mc; i += totalWarps) {
        int r = g_masked[i];
        int v = (lane < 8) ? g_contrib[r * 8 + lane] : 0;
        unsigned act = __ballot_sync(FULLM, v != 0) & 0xFFu;
        float2 acc = bv;
        while (act) {
            int t = __ffs(act) - 1;
            act &= act - 1;
            int n = __shfl_sync(FULLM, v, t) - 1;
            float f = __ldg(&feats[(long long)n * 32 + lane]);
            const float2* Wt = (const float2*)(W + t * 2048);
#pragma unroll
            for (int j = 0; j < 32; j++) {
                float fj = __shfl_sync(FULLM, f, j);
                float2 wv = __ldg(&Wt[j * 32 + lane]);
                acc.x += fj * wv.x;
                acc.y += fj * wv.y;
            }
        }
        ((float2*)(out + featBase + (long long)r * 64))[lane] = acc;
    }
}

// ---- streams/events created at load time (no device-memory allocation) -----
static cudaStream_t g_sB;
static cudaEvent_t  g_evFork, g_evEmit;
namespace {
struct ResInit {
    ResInit() {
        cudaStreamCreateWithFlags(&g_sB, cudaStreamNonBlocking);
        cudaEventCreateWithFlags(&g_evFork, cudaEventDisableTiming);
        cudaEventCreateWithFlags(&g_evEmit, cudaEventDisableTiming);
    }
};
static ResInit g_resInit;
}

extern "C" void kernel_launch(void* const* d_in, const int* in_sizes, int n_in,
                              void* d_out, int out_size) {
    const float* feats  = (const float*)d_in[0];
    const float* W      = (const float*)d_in[1];
    const float* bias   = (const float*)d_in[2];
    const int*   coords = (const int*)d_in[3];
    const int*   ref    = (const int*)d_in[4];
    float* out = (float*)d_out;

    int N  = in_sizes[3] / 4;
    int NR = in_sizes[4] / 4;
    long long featBase = 4LL * N;
    long long maskBase = (long long)out_size - N;   // == 68N
    long long featLen  = 64LL * N;                  // feats region only

    cudaEventRecord(g_evFork, 0);
    cudaStreamWaitEvent(g_sB, g_evFork, 0);

    // s0: driver fill of the feats region (A/B vs kernel fill)
    cudaMemsetAsync(out + featBase, 0, featLen * sizeof(float), 0);

    // sB: setup -> scan -> contrib
    k_setup<<<1184, 256, 0, g_sB>>>(coords, N, ref, NR);
    k_scan<<<NCHUNK, 256, 0, g_sB>>>(out, maskBase);
    k_contrib<<<1184, 256, 0, g_sB>>>(N);
    cudaEventRecord(g_evEmit, g_sB);

    // s0: join -> gather tail
    cudaStreamWaitEvent(0, g_evEmit, 0);
    k_tail<<<1184, 256, 0, 0>>>(feats, W, bias, out, N, featBase, maskBase);
}